// round 4
// baseline (speedup 1.0000x reference)
#include <cuda_runtime.h>
#include <cuda_bf16.h>
#include <cstdint>
#include <cstddef>

#define N_ROWS 8192
#define D_IN   4096
#define D_OUT  4096
#define T_TASK 10
#define RANK_  16
#define SCALING (1.0f/16.0f)

// ---------- device scratch (static: no runtime allocation) ----------
__device__ __align__(256) __nv_bfloat16 g_xh[(size_t)N_ROWS*D_IN];
__device__ __align__(256) __nv_bfloat16 g_xl[(size_t)N_ROWS*D_IN];
__device__ __align__(256) __nv_bfloat16 g_wh[(size_t)D_OUT*D_IN];
__device__ __align__(256) __nv_bfloat16 g_wl[(size_t)D_OUT*D_IN];

// ---------- helpers ----------
__device__ __forceinline__ uint32_t smem_u32(const void* p){
    return (uint32_t)__cvta_generic_to_shared(p);
}
__device__ __forceinline__ void cp16(uint32_t dst, const void* src){
    asm volatile("cp.async.cg.shared.global [%0], [%1], 16;" :: "r"(dst), "l"(src) : "memory");
}

#define LDSM4(r0,r1,r2,r3,addr) \
    asm volatile("ldmatrix.sync.aligned.m8n8.x4.shared.b16 {%0,%1,%2,%3}, [%4];" \
                 : "=r"(r0), "=r"(r1), "=r"(r2), "=r"(r3) : "r"(addr))

#define MMA16816(c,a,b) \
    asm volatile("mma.sync.aligned.m16n8k16.row.col.f32.bf16.bf16.f32 " \
                 "{%0,%1,%2,%3}, {%4,%5,%6,%7}, {%8,%9}, {%0,%1,%2,%3};" \
                 : "+f"((c)[0]), "+f"((c)[1]), "+f"((c)[2]), "+f"((c)[3]) \
                 : "r"((a)[0]), "r"((a)[1]), "r"((a)[2]), "r"((a)[3]), \
                   "r"((b)[0]), "r"((b)[1]))

// ---------- kernel 1: split x into bf16 hi/lo ----------
__global__ void __launch_bounds__(256) split_x_kernel(const float* __restrict__ x){
    size_t i = ((size_t)blockIdx.x*256u + threadIdx.x)*4u;
    float4 v = *reinterpret_cast<const float4*>(x + i);
    float f[4] = {v.x, v.y, v.z, v.w};
    __nv_bfloat16 h[4], l[4];
#pragma unroll
    for (int e=0;e<4;e++){
        h[e] = __float2bfloat16(f[e]);
        l[e] = __float2bfloat16(f[e] - __bfloat162float(h[e]));
    }
    *reinterpret_cast<uint2*>(g_xh + i) = *reinterpret_cast<uint2*>(h);
    *reinterpret_cast<uint2*>(g_xl + i) = *reinterpret_cast<uint2*>(l);
}

// ---------- kernel 2: fold LoRA into W, split hi/lo ----------
// W_eff[o,i] = W[o,i] + SCALING * sum_k Bcat[o,k]*Acat[k,i], K=160
__global__ void __launch_bounds__(256) fold_w_kernel(const float* __restrict__ W,
                                                     const float* __restrict__ lA,
                                                     const float* __restrict__ lB){
    __shared__ __align__(16) float As[32*128];
    __shared__ __align__(16) float Bs[32*128];
    const int i0 = blockIdx.x * 128;
    const int o0 = blockIdx.y * 128;
    const int tid = threadIdx.x;
    const int to = (tid >> 4) * 8;
    const int ti = (tid & 15) * 8;

    float acc[8][8];
#pragma unroll
    for (int r=0;r<8;r++)
#pragma unroll
        for (int c=0;c<8;c++) acc[r][c] = 0.f;

    for (int kb = 0; kb < 5; kb++){
        for (int idx = tid; idx < 32*128; idx += 256){
            int kl = idx >> 7, c = idx & 127;
            int kg = kb*32 + kl;
            As[idx] = lA[(size_t)kg*D_IN + i0 + c];
            Bs[idx] = lB[(size_t)(kg>>4)*((size_t)D_OUT*RANK_) + (size_t)(o0+c)*RANK_ + (kg & 15)];
        }
        __syncthreads();
#pragma unroll 2
        for (int k=0;k<32;k++){
            float4 b0 = *reinterpret_cast<float4*>(&Bs[k*128 + to]);
            float4 b1 = *reinterpret_cast<float4*>(&Bs[k*128 + to + 4]);
            float4 a0 = *reinterpret_cast<float4*>(&As[k*128 + ti]);
            float4 a1 = *reinterpret_cast<float4*>(&As[k*128 + ti + 4]);
            float bv[8] = {b0.x,b0.y,b0.z,b0.w,b1.x,b1.y,b1.z,b1.w};
            float av[8] = {a0.x,a0.y,a0.z,a0.w,a1.x,a1.y,a1.z,a1.w};
#pragma unroll
            for (int r=0;r<8;r++)
#pragma unroll
                for (int c=0;c<8;c++) acc[r][c] += bv[r]*av[c];
        }
        __syncthreads();
    }

#pragma unroll
    for (int r=0;r<8;r++){
        int o = o0 + to + r;
        const float* wrow = W + (size_t)o*D_IN + i0 + ti;
        float4 w0 = *reinterpret_cast<const float4*>(wrow);
        float4 w1 = *reinterpret_cast<const float4*>(wrow + 4);
        float wv[8] = {w0.x,w0.y,w0.z,w0.w,w1.x,w1.y,w1.z,w1.w};
        __nv_bfloat16 hv[8], lv[8];
#pragma unroll
        for (int c=0;c<8;c++){
            float we = wv[c] + acc[r][c]*SCALING;
            hv[c] = __float2bfloat16(we);
            lv[c] = __float2bfloat16(we - __bfloat162float(hv[c]));
        }
        size_t off = (size_t)o*D_IN + i0 + ti;
        *reinterpret_cast<uint4*>(g_wh + off) = *reinterpret_cast<uint4*>(hv);
        *reinterpret_cast<uint4*>(g_wl + off) = *reinterpret_cast<uint4*>(lv);
    }
}

// ---------- kernel 3: main GEMM via mma.sync (bf16, fp32 accum) ----------
// CTA tile 128(M) x 256(N), 8 warps (2 wm x 4 wn), warp tile 64x64.
// K chunks of 64 bf16; effective K = 3*4096 via segments (xh*wh, xl*wh, xh*wl).
// 4-stage cp.async pipeline, ONE __syncthreads per chunk.
// smem rows padded to 144B (conflict-free ldmatrix).
#define MT 128
#define NT 256
#define SROW 144
#define A_ST (MT*SROW)                 // 18432
#define B_ST (NT*SROW)                 // 36864
#define STG  (A_ST + B_ST)             // 55296
#define NSTAGE 4
#define GEMM_SMEM (NSTAGE*STG)         // 221184
#define NKI 192

__global__ void __launch_bounds__(256, 1)
lora_gemm_kernel(const float* __restrict__ bias, float* __restrict__ out){
    extern __shared__ char smem[];
    const uint32_t sbase = smem_u32(smem);
    const int tid = threadIdx.x;
    const int wid = tid >> 5;
    const int l   = tid & 31;
    const int wm  = wid >> 2;   // 2 M-groups of 64
    const int wn  = wid & 3;    // 4 N-groups of 64
    const int m0  = (int)(blockIdx.x >> 4) * MT;
    const int n0  = (int)(blockIdx.x & 15) * NT;

    float acc[4][8][4];
#pragma unroll
    for (int mi=0;mi<4;mi++)
#pragma unroll
        for (int nj=0;nj<8;nj++)
#pragma unroll
            for (int e=0;e<4;e++) acc[mi][nj][e] = 0.f;

    // per-thread load assignment:
    // A: 128 rows x 128B, 2 thr/row, 4x16B each
    // B: 256 rows x 128B, 1 thr/row, 8x16B each
    const int arow = tid >> 1, ah = tid & 1;

    auto issue_load = [&](int kk){
        const int seg = kk >> 6;
        const int k0  = (kk & 63) << 6;
        const __nv_bfloat16* Asrc = (seg == 1) ? g_xl : g_xh;
        const __nv_bfloat16* Bsrc = (seg == 2) ? g_wl : g_wh;
        const uint32_t as = sbase + (uint32_t)(kk % NSTAGE) * STG;
        const uint32_t bs = as + A_ST;
        const __nv_bfloat16* ga = Asrc + (size_t)(m0 + arow)*D_IN + k0 + ah*32;
        const uint32_t adst = as + (uint32_t)arow*SROW + (uint32_t)ah*64;
#pragma unroll
        for (int c=0;c<4;c++) cp16(adst + c*16, ga + c*8);
        const __nv_bfloat16* gb = Bsrc + (size_t)(n0 + tid)*D_IN + k0;
        const uint32_t bdst = bs + (uint32_t)tid*SROW;
#pragma unroll
        for (int c=0;c<8;c++) cp16(bdst + c*16, gb + c*8);
        asm volatile("cp.async.commit_group;" ::: "memory");
    };

    issue_load(0);
    issue_load(1);
    issue_load(2);

    // ldmatrix lane addressing
    const uint32_t a_lane = (uint32_t)(wm*64 + (l & 15)) * SROW + (uint32_t)((l >> 4) & 1) * 16;
    const uint32_t b_lane = (uint32_t)(wn*64 + (l & 7) + ((l >> 4) & 1)*8) * SROW
                          + (uint32_t)((l >> 3) & 1) * 16;

    for (int kk = 0; kk < NKI; kk++){
        asm volatile("cp.async.wait_group 2;" ::: "memory");
        __syncthreads();

        if (kk + 3 < NKI) issue_load(kk + 3);
        else asm volatile("cp.async.commit_group;" ::: "memory");

        const uint32_t as = sbase + (uint32_t)(kk % NSTAGE) * STG;
        const uint32_t bs = as + A_ST;

#pragma unroll
        for (int ks = 0; ks < 4; ks++){
            uint32_t a[4][4];
#pragma unroll
            for (int mi=0;mi<4;mi++){
                uint32_t addr = as + a_lane + (uint32_t)(mi*16)*SROW + (uint32_t)ks*32;
                LDSM4(a[mi][0], a[mi][1], a[mi][2], a[mi][3], addr);
            }
            uint32_t b[8][2];
#pragma unroll
            for (int nb=0;nb<4;nb++){
                uint32_t addr = bs + b_lane + (uint32_t)(nb*16)*SROW + (uint32_t)ks*32;
                LDSM4(b[2*nb][0], b[2*nb][1], b[2*nb+1][0], b[2*nb+1][1], addr);
            }
#pragma unroll
            for (int mi=0;mi<4;mi++)
#pragma unroll
                for (int nj=0;nj<8;nj++)
                    MMA16816(acc[mi][nj], a[mi], b[nj]);
        }
    }

    // epilogue: add bias, store fp32
#pragma unroll
    for (int mi=0;mi<4;mi++){
        const int m = m0 + wm*64 + mi*16 + (l >> 2);
#pragma unroll
        for (int nj=0;nj<8;nj++){
            const int n = n0 + wn*64 + nj*8 + (l & 3)*2;
            const float b0 = bias[n], b1 = bias[n+1];
            float2 v0 = make_float2(acc[mi][nj][0] + b0, acc[mi][nj][1] + b1);
            float2 v1 = make_float2(acc[mi][nj][2] + b0, acc[mi][nj][3] + b1);
            *reinterpret_cast<float2*>(out + (size_t)m*D_OUT + n)       = v0;
            *reinterpret_cast<float2*>(out + (size_t)(m+8)*D_OUT + n)   = v1;
        }
    }
}

// ---------- launch ----------
extern "C" void kernel_launch(void* const* d_in, const int* in_sizes, int n_in,
                              void* d_out, int out_size){
    const float* x  = (const float*)d_in[0];
    const float* W  = (const float*)d_in[1];
    const float* b  = (const float*)d_in[2];
    const float* lA = (const float*)d_in[3];
    const float* lB = (const float*)d_in[4];
    float* out = (float*)d_out;

    static bool attr_set = false;
    if (!attr_set){
        cudaFuncSetAttribute(lora_gemm_kernel,
                             cudaFuncAttributeMaxDynamicSharedMemorySize, GEMM_SMEM);
        attr_set = true;
    }

    split_x_kernel<<<(size_t)N_ROWS*D_IN/4/256, 256>>>(x);
    fold_w_kernel<<<dim3(D_IN/128, D_OUT/128), 256>>>(W, lA, lB);
    lora_gemm_kernel<<<(N_ROWS/MT)*(D_OUT/NT), 256, GEMM_SMEM>>>(b, out);
}

// round 5
// speedup vs baseline: 1.7287x; 1.7287x over previous
#include <cuda_runtime.h>
#include <cuda_fp16.h>
#include <cstdint>
#include <cstddef>

#define N_ROWS 8192
#define D_IN   4096
#define D_OUT  4096
#define T_TASK 10
#define RANK_  16
#define SCALING (1.0f/16.0f)

// ---------- device scratch (static: no runtime allocation) ----------
__device__ __align__(256) __half g_xh[(size_t)N_ROWS*D_IN];
__device__ __align__(256) __half g_xl[(size_t)N_ROWS*D_IN];
__device__ __align__(256) __half g_wh[(size_t)D_OUT*D_IN];

// ---------- helpers ----------
__device__ __forceinline__ uint32_t smem_u32(const void* p){
    return (uint32_t)__cvta_generic_to_shared(p);
}
__device__ __forceinline__ void cp16(uint32_t dst, const void* src){
    asm volatile("cp.async.cg.shared.global [%0], [%1], 16;" :: "r"(dst), "l"(src) : "memory");
}

#define LDSM4(r0,r1,r2,r3,addr) \
    asm volatile("ldmatrix.sync.aligned.m8n8.x4.shared.b16 {%0,%1,%2,%3}, [%4];" \
                 : "=r"(r0), "=r"(r1), "=r"(r2), "=r"(r3) : "r"(addr))

#define MMA16816(c,a,b) \
    asm volatile("mma.sync.aligned.m16n8k16.row.col.f32.f16.f16.f32 " \
                 "{%0,%1,%2,%3}, {%4,%5,%6,%7}, {%8,%9}, {%0,%1,%2,%3};" \
                 : "+f"((c)[0]), "+f"((c)[1]), "+f"((c)[2]), "+f"((c)[3]) \
                 : "r"((a)[0]), "r"((a)[1]), "r"((a)[2]), "r"((a)[3]), \
                   "r"((b)[0]), "r"((b)[1]))

// ---------- kernel 1: split x into fp16 hi/lo ----------
__global__ void __launch_bounds__(256) split_x_kernel(const float* __restrict__ x){
    size_t i = ((size_t)blockIdx.x*256u + threadIdx.x)*4u;
    float4 v = *reinterpret_cast<const float4*>(x + i);
    float f[4] = {v.x, v.y, v.z, v.w};
    __half h[4], l[4];
#pragma unroll
    for (int e=0;e<4;e++){
        h[e] = __float2half(f[e]);
        l[e] = __float2half(f[e] - __half2float(h[e]));
    }
    *reinterpret_cast<uint2*>(g_xh + i) = *reinterpret_cast<uint2*>(h);
    *reinterpret_cast<uint2*>(g_xl + i) = *reinterpret_cast<uint2*>(l);
}

// ---------- kernel 2: fold LoRA into W, convert to fp16 ----------
// W_eff[o,i] = W[o,i] + SCALING * sum_k Bcat[o,k]*Acat[k,i], K=160
__global__ void __launch_bounds__(256) fold_w_kernel(const float* __restrict__ W,
                                                     const float* __restrict__ lA,
                                                     const float* __restrict__ lB){
    __shared__ __align__(16) float As[32*128];
    __shared__ __align__(16) float Bs[32*128];
    const int i0 = blockIdx.x * 128;
    const int o0 = blockIdx.y * 128;
    const int tid = threadIdx.x;
    const int to = (tid >> 4) * 8;
    const int ti = (tid & 15) * 8;

    float acc[8][8];
#pragma unroll
    for (int r=0;r<8;r++)
#pragma unroll
        for (int c=0;c<8;c++) acc[r][c] = 0.f;

    for (int kb = 0; kb < 5; kb++){
        for (int idx = tid; idx < 32*128; idx += 256){
            int kl = idx >> 7, c = idx & 127;
            int kg = kb*32 + kl;
            As[idx] = lA[(size_t)kg*D_IN + i0 + c];
            Bs[idx] = lB[(size_t)(kg>>4)*((size_t)D_OUT*RANK_) + (size_t)(o0+c)*RANK_ + (kg & 15)];
        }
        __syncthreads();
#pragma unroll 2
        for (int k=0;k<32;k++){
            float4 b0 = *reinterpret_cast<float4*>(&Bs[k*128 + to]);
            float4 b1 = *reinterpret_cast<float4*>(&Bs[k*128 + to + 4]);
            float4 a0 = *reinterpret_cast<float4*>(&As[k*128 + ti]);
            float4 a1 = *reinterpret_cast<float4*>(&As[k*128 + ti + 4]);
            float bv[8] = {b0.x,b0.y,b0.z,b0.w,b1.x,b1.y,b1.z,b1.w};
            float av[8] = {a0.x,a0.y,a0.z,a0.w,a1.x,a1.y,a1.z,a1.w};
#pragma unroll
            for (int r=0;r<8;r++)
#pragma unroll
                for (int c=0;c<8;c++) acc[r][c] += bv[r]*av[c];
        }
        __syncthreads();
    }

#pragma unroll
    for (int r=0;r<8;r++){
        int o = o0 + to + r;
        const float* wrow = W + (size_t)o*D_IN + i0 + ti;
        float4 w0 = *reinterpret_cast<const float4*>(wrow);
        float4 w1 = *reinterpret_cast<const float4*>(wrow + 4);
        float wv[8] = {w0.x,w0.y,w0.z,w0.w,w1.x,w1.y,w1.z,w1.w};
        __half hv[8];
#pragma unroll
        for (int c=0;c<8;c++)
            hv[c] = __float2half(wv[c] + acc[r][c]*SCALING);
        size_t off = (size_t)o*D_IN + i0 + ti;
        *reinterpret_cast<uint4*>(g_wh + off) = *reinterpret_cast<uint4*>(hv);
    }
}

// ---------- kernel 3: main GEMM via mma.sync (fp16, fp32 accum) ----------
// CTA tile 256(M) x 128(N), 16 warps (4x4), warp tile 64x32.
// K chunks of 64 fp16; effective K = 2*4096: segments (xh*wh, xl*wh).
// 4-stage cp.async ring, ONE __syncthreads per chunk.
// smem rows padded to 144B for conflict-free ldmatrix/cp.async.
#define MT 256
#define NT 128
#define SROW 144
#define A_ST (MT*SROW)                 // 36864
#define B_ST (NT*SROW)                 // 18432
#define STG  (A_ST + B_ST)             // 55296
#define NSTAGE 4
#define GEMM_SMEM (NSTAGE*STG)         // 221184
#define NKI 128

__global__ void __launch_bounds__(512, 1)
lora_gemm_kernel(const float* __restrict__ bias, float* __restrict__ out){
    extern __shared__ char smem[];
    const uint32_t sbase = smem_u32(smem);
    const int tid = threadIdx.x;
    const int wid = tid >> 5;
    const int l   = tid & 31;
    const int wm  = wid & 3;    // 4 M-groups of 64
    const int wn  = wid >> 2;   // 4 N-groups of 32
    const int m0  = (int)(blockIdx.x >> 5) * MT;
    const int n0  = (int)(blockIdx.x & 31) * NT;

    float acc[4][4][4];
#pragma unroll
    for (int mi=0;mi<4;mi++)
#pragma unroll
        for (int nj=0;nj<4;nj++)
#pragma unroll
            for (int e=0;e<4;e++) acc[mi][nj][e] = 0.f;

    // per-thread load assignment
    const int arow = tid >> 1, ah = tid & 1;       // A: 256 rows, 2 thr/row, 4x16B each
    const int brow = tid >> 2, bq = tid & 3;       // B: 128 rows, 4 thr/row, 2x16B each

    auto issue_load = [&](int kk){
        const int seg = kk >> 6;
        const int k0  = (kk & 63) << 6;
        const __half* Asrc = seg ? g_xl : g_xh;
        const uint32_t as = sbase + (uint32_t)(kk % NSTAGE) * STG;
        const uint32_t bs = as + A_ST;
        const __half* ga = Asrc + (size_t)(m0 + arow)*D_IN + k0 + ah*32;
        const uint32_t adst = as + (uint32_t)arow*SROW + (uint32_t)ah*64;
#pragma unroll
        for (int c=0;c<4;c++) cp16(adst + c*16, ga + c*8);
        const __half* gb = g_wh + (size_t)(n0 + brow)*D_IN + k0 + bq*16;
        const uint32_t bdst = bs + (uint32_t)brow*SROW + (uint32_t)bq*32;
#pragma unroll
        for (int c=0;c<2;c++) cp16(bdst + c*16, gb + c*8);
        asm volatile("cp.async.commit_group;" ::: "memory");
    };

    issue_load(0);
    issue_load(1);
    issue_load(2);

    // ldmatrix lane addressing
    const uint32_t a_lane = (uint32_t)(wm*64 + (l & 15)) * SROW + (uint32_t)((l >> 4) & 1) * 16;
    const uint32_t b_lane = (uint32_t)(wn*32 + (l & 7) + ((l >> 4) & 1)*8) * SROW
                          + (uint32_t)((l >> 3) & 1) * 16;

    for (int kk = 0; kk < NKI; kk++){
        asm volatile("cp.async.wait_group 2;" ::: "memory");
        __syncthreads();

        if (kk + 3 < NKI) issue_load(kk + 3);
        else asm volatile("cp.async.commit_group;" ::: "memory");

        const uint32_t as = sbase + (uint32_t)(kk % NSTAGE) * STG;
        const uint32_t bs = as + A_ST;

#pragma unroll
        for (int ks = 0; ks < 4; ks++){
            uint32_t a[4][4];
#pragma unroll
            for (int mi=0;mi<4;mi++){
                uint32_t addr = as + a_lane + (uint32_t)(mi*16)*SROW + (uint32_t)ks*32;
                LDSM4(a[mi][0], a[mi][1], a[mi][2], a[mi][3], addr);
            }
            uint32_t b[4][2];
#pragma unroll
            for (int nb=0;nb<2;nb++){
                uint32_t addr = bs + b_lane + (uint32_t)(nb*16)*SROW + (uint32_t)ks*32;
                LDSM4(b[2*nb][0], b[2*nb][1], b[2*nb+1][0], b[2*nb+1][1], addr);
            }
#pragma unroll
            for (int mi=0;mi<4;mi++)
#pragma unroll
                for (int nj=0;nj<4;nj++)
                    MMA16816(acc[mi][nj], a[mi], b[nj]);
        }
    }

    // epilogue: add bias, store fp32
#pragma unroll
    for (int mi=0;mi<4;mi++){
        const int m = m0 + wm*64 + mi*16 + (l >> 2);
#pragma unroll
        for (int nj=0;nj<4;nj++){
            const int n = n0 + wn*32 + nj*8 + (l & 3)*2;
            const float b0 = bias[n], b1 = bias[n+1];
            float2 v0 = make_float2(acc[mi][nj][0] + b0, acc[mi][nj][1] + b1);
            float2 v1 = make_float2(acc[mi][nj][2] + b0, acc[mi][nj][3] + b1);
            *reinterpret_cast<float2*>(out + (size_t)m*D_OUT + n)       = v0;
            *reinterpret_cast<float2*>(out + (size_t)(m+8)*D_OUT + n)   = v1;
        }
    }
}

// ---------- launch ----------
extern "C" void kernel_launch(void* const* d_in, const int* in_sizes, int n_in,
                              void* d_out, int out_size){
    const float* x  = (const float*)d_in[0];
    const float* W  = (const float*)d_in[1];
    const float* b  = (const float*)d_in[2];
    const float* lA = (const float*)d_in[3];
    const float* lB = (const float*)d_in[4];
    float* out = (float*)d_out;

    static bool attr_set = false;
    if (!attr_set){
        cudaFuncSetAttribute(lora_gemm_kernel,
                             cudaFuncAttributeMaxDynamicSharedMemorySize, GEMM_SMEM);
        attr_set = true;
    }

    // order: fold, split, gemm — so ncu (-s 5 -c 1) lands on the GEMM
    fold_w_kernel<<<dim3(D_IN/128, D_OUT/128), 256>>>(W, lA, lB);
    split_x_kernel<<<(size_t)N_ROWS*D_IN/4/256, 256>>>(x);
    lora_gemm_kernel<<<(N_ROWS/MT)*(D_OUT/NT), 512, GEMM_SMEM>>>(b, out);
}

// round 6
// speedup vs baseline: 3.1609x; 1.8285x over previous
#include <cuda_runtime.h>
#include <cuda_fp16.h>
#include <cstdint>
#include <cstddef>

#define N_ROWS 8192
#define D_IN   4096
#define D_OUT  4096
#define T_TASK 10
#define RANK_  16
#define SCALING (1.0f/16.0f)

// ---------- device scratch (static: no runtime allocation) ----------
__device__ __align__(256) __half g_xh[(size_t)N_ROWS*D_IN];
__device__ __align__(256) __half g_wh[(size_t)D_OUT*D_IN];

// ---------- helpers ----------
__device__ __forceinline__ uint32_t smem_u32(const void* p){
    return (uint32_t)__cvta_generic_to_shared(p);
}
__device__ __forceinline__ void cp16(uint32_t dst, const void* src){
    asm volatile("cp.async.cg.shared.global [%0], [%1], 16;" :: "r"(dst), "l"(src) : "memory");
}

#define LDSM4(r0,r1,r2,r3,addr) \
    asm volatile("ldmatrix.sync.aligned.m8n8.x4.shared.b16 {%0,%1,%2,%3}, [%4];" \
                 : "=r"(r0), "=r"(r1), "=r"(r2), "=r"(r3) : "r"(addr))

#define MMA16816(c,a,b) \
    asm volatile("mma.sync.aligned.m16n8k16.row.col.f32.f16.f16.f32 " \
                 "{%0,%1,%2,%3}, {%4,%5,%6,%7}, {%8,%9}, {%0,%1,%2,%3};" \
                 : "+f"((c)[0]), "+f"((c)[1]), "+f"((c)[2]), "+f"((c)[3]) \
                 : "r"((a)[0]), "r"((a)[1]), "r"((a)[2]), "r"((a)[3]), \
                   "r"((b)[0]), "r"((b)[1]))

// ---------- kernel 1: convert x to fp16 ----------
__global__ void __launch_bounds__(256) split_x_kernel(const float* __restrict__ x){
    size_t i = ((size_t)blockIdx.x*256u + threadIdx.x)*4u;
    float4 v = *reinterpret_cast<const float4*>(x + i);
    float f[4] = {v.x, v.y, v.z, v.w};
    __half h[4];
#pragma unroll
    for (int e=0;e<4;e++) h[e] = __float2half(f[e]);
    *reinterpret_cast<uint2*>(g_xh + i) = *reinterpret_cast<uint2*>(h);
}

// ---------- kernel 2: fold LoRA into W, convert to fp16 ----------
// W_eff[o,i] = W[o,i] + SCALING * sum_k Bcat[o,k]*Acat[k,i], K=160
__global__ void __launch_bounds__(256) fold_w_kernel(const float* __restrict__ W,
                                                     const float* __restrict__ lA,
                                                     const float* __restrict__ lB){
    __shared__ __align__(16) float As[32*128];
    __shared__ __align__(16) float Bs[32*128];
    const int i0 = blockIdx.x * 128;
    const int o0 = blockIdx.y * 128;
    const int tid = threadIdx.x;
    const int to = (tid >> 4) * 8;
    const int ti = (tid & 15) * 8;

    float acc[8][8];
#pragma unroll
    for (int r=0;r<8;r++)
#pragma unroll
        for (int c=0;c<8;c++) acc[r][c] = 0.f;

    for (int kb = 0; kb < 5; kb++){
        for (int idx = tid; idx < 32*128; idx += 256){
            int kl = idx >> 7, c = idx & 127;
            int kg = kb*32 + kl;
            As[idx] = lA[(size_t)kg*D_IN + i0 + c];
            Bs[idx] = lB[(size_t)(kg>>4)*((size_t)D_OUT*RANK_) + (size_t)(o0+c)*RANK_ + (kg & 15)];
        }
        __syncthreads();
#pragma unroll 2
        for (int k=0;k<32;k++){
            float4 b0 = *reinterpret_cast<float4*>(&Bs[k*128 + to]);
            float4 b1 = *reinterpret_cast<float4*>(&Bs[k*128 + to + 4]);
            float4 a0 = *reinterpret_cast<float4*>(&As[k*128 + ti]);
            float4 a1 = *reinterpret_cast<float4*>(&As[k*128 + ti + 4]);
            float bv[8] = {b0.x,b0.y,b0.z,b0.w,b1.x,b1.y,b1.z,b1.w};
            float av[8] = {a0.x,a0.y,a0.z,a0.w,a1.x,a1.y,a1.z,a1.w};
#pragma unroll
            for (int r=0;r<8;r++)
#pragma unroll
                for (int c=0;c<8;c++) acc[r][c] += bv[r]*av[c];
        }
        __syncthreads();
    }

#pragma unroll
    for (int r=0;r<8;r++){
        int o = o0 + to + r;
        const float* wrow = W + (size_t)o*D_IN + i0 + ti;
        float4 w0 = *reinterpret_cast<const float4*>(wrow);
        float4 w1 = *reinterpret_cast<const float4*>(wrow + 4);
        float wv[8] = {w0.x,w0.y,w0.z,w0.w,w1.x,w1.y,w1.z,w1.w};
        __half hv[8];
#pragma unroll
        for (int c=0;c<8;c++)
            hv[c] = __float2half(wv[c] + acc[r][c]*SCALING);
        size_t off = (size_t)o*D_IN + i0 + ti;
        *reinterpret_cast<uint4*>(g_wh + off) = *reinterpret_cast<uint4*>(hv);
    }
}

// ---------- kernel 3: main GEMM via mma.sync (fp16, fp32 accum) ----------
// CTA tile 256(M) x 128(N), 16 warps (4x4), warp tile 64x32.
// K chunks of 64 fp16; K = 4096 (single xh*wh pass).
// 4-stage cp.async ring, ONE __syncthreads per chunk.
// smem rows padded to 144B for conflict-free ldmatrix/cp.async.
#define MT 256
#define NT 128
#define SROW 144
#define A_ST (MT*SROW)                 // 36864
#define B_ST (NT*SROW)                 // 18432
#define STG  (A_ST + B_ST)             // 55296
#define NSTAGE 4
#define GEMM_SMEM (NSTAGE*STG)         // 221184
#define NKI 64

__global__ void __launch_bounds__(512, 1)
lora_gemm_kernel(const float* __restrict__ bias, float* __restrict__ out){
    extern __shared__ char smem[];
    const uint32_t sbase = smem_u32(smem);
    const int tid = threadIdx.x;
    const int wid = tid >> 5;
    const int l   = tid & 31;
    const int wm  = wid & 3;    // 4 M-groups of 64
    const int wn  = wid >> 2;   // 4 N-groups of 32
    const int m0  = (int)(blockIdx.x >> 5) * MT;
    const int n0  = (int)(blockIdx.x & 31) * NT;

    float acc[4][4][4];
#pragma unroll
    for (int mi=0;mi<4;mi++)
#pragma unroll
        for (int nj=0;nj<4;nj++)
#pragma unroll
            for (int e=0;e<4;e++) acc[mi][nj][e] = 0.f;

    // per-thread load assignment
    const int arow = tid >> 1, ah = tid & 1;       // A: 256 rows, 2 thr/row, 4x16B each
    const int brow = tid >> 2, bq = tid & 3;       // B: 128 rows, 4 thr/row, 2x16B each

    auto issue_load = [&](int kk){
        const int k0  = kk << 6;
        const uint32_t as = sbase + (uint32_t)(kk % NSTAGE) * STG;
        const uint32_t bs = as + A_ST;
        const __half* ga = g_xh + (size_t)(m0 + arow)*D_IN + k0 + ah*32;
        const uint32_t adst = as + (uint32_t)arow*SROW + (uint32_t)ah*64;
#pragma unroll
        for (int c=0;c<4;c++) cp16(adst + c*16, ga + c*8);
        const __half* gb = g_wh + (size_t)(n0 + brow)*D_IN + k0 + bq*16;
        const uint32_t bdst = bs + (uint32_t)brow*SROW + (uint32_t)bq*32;
#pragma unroll
        for (int c=0;c<2;c++) cp16(bdst + c*16, gb + c*8);
        asm volatile("cp.async.commit_group;" ::: "memory");
    };

    issue_load(0);
    issue_load(1);
    issue_load(2);

    // ldmatrix lane addressing
    const uint32_t a_lane = (uint32_t)(wm*64 + (l & 15)) * SROW + (uint32_t)((l >> 4) & 1) * 16;
    const uint32_t b_lane = (uint32_t)(wn*32 + (l & 7) + ((l >> 4) & 1)*8) * SROW
                          + (uint32_t)((l >> 3) & 1) * 16;

    for (int kk = 0; kk < NKI; kk++){
        asm volatile("cp.async.wait_group 2;" ::: "memory");
        __syncthreads();

        if (kk + 3 < NKI) issue_load(kk + 3);
        else asm volatile("cp.async.commit_group;" ::: "memory");

        const uint32_t as = sbase + (uint32_t)(kk % NSTAGE) * STG;
        const uint32_t bs = as + A_ST;

#pragma unroll
        for (int ks = 0; ks < 4; ks++){
            uint32_t a[4][4];
#pragma unroll
            for (int mi=0;mi<4;mi++){
                uint32_t addr = as + a_lane + (uint32_t)(mi*16)*SROW + (uint32_t)ks*32;
                LDSM4(a[mi][0], a[mi][1], a[mi][2], a[mi][3], addr);
            }
            uint32_t b[4][2];
#pragma unroll
            for (int nb=0;nb<2;nb++){
                uint32_t addr = bs + b_lane + (uint32_t)(nb*16)*SROW + (uint32_t)ks*32;
                LDSM4(b[2*nb][0], b[2*nb][1], b[2*nb+1][0], b[2*nb+1][1], addr);
            }
#pragma unroll
            for (int mi=0;mi<4;mi++)
#pragma unroll
                for (int nj=0;nj<4;nj++)
                    MMA16816(acc[mi][nj], a[mi], b[nj]);
        }
    }

    // epilogue: add bias, store fp32
#pragma unroll
    for (int mi=0;mi<4;mi++){
        const int m = m0 + wm*64 + mi*16 + (l >> 2);
#pragma unroll
        for (int nj=0;nj<4;nj++){
            const int n = n0 + wn*32 + nj*8 + (l & 3)*2;
            const float b0 = bias[n], b1 = bias[n+1];
            float2 v0 = make_float2(acc[mi][nj][0] + b0, acc[mi][nj][1] + b1);
            float2 v1 = make_float2(acc[mi][nj][2] + b0, acc[mi][nj][3] + b1);
            *reinterpret_cast<float2*>(out + (size_t)m*D_OUT + n)       = v0;
            *reinterpret_cast<float2*>(out + (size_t)(m+8)*D_OUT + n)   = v1;
        }
    }
}

// ---------- launch ----------
extern "C" void kernel_launch(void* const* d_in, const int* in_sizes, int n_in,
                              void* d_out, int out_size){
    const float* x  = (const float*)d_in[0];
    const float* W  = (const float*)d_in[1];
    const float* b  = (const float*)d_in[2];
    const float* lA = (const float*)d_in[3];
    const float* lB = (const float*)d_in[4];
    float* out = (float*)d_out;

    static bool attr_set = false;
    if (!attr_set){
        cudaFuncSetAttribute(lora_gemm_kernel,
                             cudaFuncAttributeMaxDynamicSharedMemorySize, GEMM_SMEM);
        attr_set = true;
    }

    // order: fold, split, gemm — so ncu (-s 5 -c 1) lands on the GEMM
    fold_w_kernel<<<dim3(D_IN/128, D_OUT/128), 256>>>(W, lA, lB);
    split_x_kernel<<<(size_t)N_ROWS*D_IN/4/256, 256>>>(x);
    lora_gemm_kernel<<<(N_ROWS/MT)*(D_OUT/NT), 512, GEMM_SMEM>>>(b, out);
}

// round 7
// speedup vs baseline: 3.5031x; 1.1083x over previous
#include <cuda_runtime.h>
#include <cuda_fp16.h>
#include <cstdint>
#include <cstddef>

#define N_ROWS 8192
#define D_IN   4096
#define D_OUT  4096
#define T_TASK 10
#define RANK_  16
#define K_LORA 160
#define SCALING (1.0f/16.0f)

// ---------- device scratch (static: no runtime allocation) ----------
__device__ __align__(256) __half g_xh[(size_t)N_ROWS*D_IN];
__device__ __align__(256) __half g_wh[(size_t)D_OUT*D_IN];
__device__ __align__(256) __half g_ahT[(size_t)D_IN*K_LORA];   // AhT[i][k] = Acat[k][i]
__device__ __align__(256) __half g_bh [(size_t)D_OUT*K_LORA];  // Bh[o][k]  = Bcat[o][k]

// ---------- helpers ----------
__device__ __forceinline__ uint32_t smem_u32(const void* p){
    return (uint32_t)__cvta_generic_to_shared(p);
}
__device__ __forceinline__ void cp16(uint32_t dst, const void* src){
    asm volatile("cp.async.cg.shared.global [%0], [%1], 16;" :: "r"(dst), "l"(src) : "memory");
}

#define LDSM4(r0,r1,r2,r3,addr) \
    asm volatile("ldmatrix.sync.aligned.m8n8.x4.shared.b16 {%0,%1,%2,%3}, [%4];" \
                 : "=r"(r0), "=r"(r1), "=r"(r2), "=r"(r3) : "r"(addr))

#define MMA16816(c,a,b) \
    asm volatile("mma.sync.aligned.m16n8k16.row.col.f32.f16.f16.f32 " \
                 "{%0,%1,%2,%3}, {%4,%5,%6,%7}, {%8,%9}, {%0,%1,%2,%3};" \
                 : "+f"((c)[0]), "+f"((c)[1]), "+f"((c)[2]), "+f"((c)[3]) \
                 : "r"((a)[0]), "r"((a)[1]), "r"((a)[2]), "r"((a)[3]), \
                   "r"((b)[0]), "r"((b)[1]))

// ---------- kernel P1: convert lA (transposed) and lB to fp16 ----------
__global__ void __launch_bounds__(256) prep_kernel(const float* __restrict__ lA,
                                                   const float* __restrict__ lB){
    const size_t TOT = (size_t)D_IN * K_LORA;   // 655360
    size_t gid = (size_t)blockIdx.x*256u + threadIdx.x;
    if (gid < TOT){
        int i = (int)(gid / K_LORA), k = (int)(gid % K_LORA);
        // lA flattened [T,R,D_IN] -> Acat[k][i] at k*D_IN + i
        g_ahT[gid] = __float2half(lA[(size_t)k*D_IN + i]);
    } else if (gid < 2*TOT){
        size_t g = gid - TOT;
        int o = (int)(g / K_LORA), k = (int)(g % K_LORA);
        int t = k >> 4, r = k & 15;
        // lB flattened [T,D_OUT,R]
        g_bh[g] = __float2half(lB[(size_t)t*D_OUT*RANK_ + (size_t)o*RANK_ + r]);
    }
}

// ---------- kernel P2: tensor-core fold (blocks 0..1023) + x->fp16 convert (1024..1535) ----------
// Fold tile: 128(o) x 128(i), K=160 fp16 via mma.sync, epilogue adds W and writes g_wh.
#define FROW 336                       // 160*2 + 16 pad
#define F_ST (128*FROW)                // 43008
#define FOLD_SMEM (2*F_ST)             // 86016
#define NCONV 512

__global__ void __launch_bounds__(256)
fold_x_kernel(const float* __restrict__ W, const float* __restrict__ x){
    if (blockIdx.x >= 1024){
        // ---- x conversion: grid-stride float4 ----
        size_t tbase = (size_t)(blockIdx.x - 1024)*256u + threadIdx.x;
        const size_t nthreads = (size_t)NCONV*256u;                 // 131072
        const size_t nf4 = (size_t)N_ROWS*D_IN/4;                   // 8388608
        for (size_t i4 = tbase; i4 < nf4; i4 += nthreads){
            size_t i = i4*4;
            float4 v = *reinterpret_cast<const float4*>(x + i);
            __half h[4];
            h[0]=__float2half(v.x); h[1]=__float2half(v.y);
            h[2]=__float2half(v.z); h[3]=__float2half(v.w);
            *reinterpret_cast<uint2*>(g_xh + i) = *reinterpret_cast<uint2*>(h);
        }
        return;
    }
    // ---- fold tile ----
    extern __shared__ char fsm[];
    const uint32_t sa = smem_u32(fsm);
    const uint32_t sb = sa + F_ST;
    const int tid = threadIdx.x;
    const int wid = tid >> 5;
    const int l   = tid & 31;
    const int wm  = wid & 3;    // 4 M-groups? no: 8 warps = 2(M) x 4(N)
    const int wmn = wid >> 2;   // 2 M-groups of 64
    const int wnn = wid & 3;    // 4 N-groups of 32
    const int o0  = (int)(blockIdx.x >> 5) * 128;
    const int i0  = (int)(blockIdx.x & 31) * 128;
    (void)wm;

    // load: A = Bh rows o0..o0+127, B = AhT rows i0..i0+127; 320B per row
    {
        const int row = tid >> 1, hf = tid & 1;
        const __half* gA = g_bh  + (size_t)(o0 + row)*K_LORA + hf*80;
        const __half* gB = g_ahT + (size_t)(i0 + row)*K_LORA + hf*80;
        const uint32_t da = sa + (uint32_t)row*FROW + (uint32_t)hf*160;
        const uint32_t db = sb + (uint32_t)row*FROW + (uint32_t)hf*160;
#pragma unroll
        for (int c=0;c<10;c++) cp16(da + c*16, gA + c*8);
#pragma unroll
        for (int c=0;c<10;c++) cp16(db + c*16, gB + c*8);
    }
    asm volatile("cp.async.commit_group;\n\tcp.async.wait_group 0;" ::: "memory");
    __syncthreads();

    float acc[4][4][4];
#pragma unroll
    for (int mi=0;mi<4;mi++)
#pragma unroll
        for (int nj=0;nj<4;nj++)
#pragma unroll
            for (int e=0;e<4;e++) acc[mi][nj][e] = 0.f;

    const uint32_t a_lane = (uint32_t)(wmn*64 + (l & 15)) * FROW + (uint32_t)((l >> 4) & 1) * 16;
    const uint32_t b_lane = (uint32_t)(wnn*32 + (l & 7) + ((l >> 4) & 1)*8) * FROW
                          + (uint32_t)((l >> 3) & 1) * 16;

#pragma unroll
    for (int ks = 0; ks < 10; ks++){
        uint32_t a[4][4];
#pragma unroll
        for (int mi=0;mi<4;mi++){
            uint32_t addr = sa + a_lane + (uint32_t)(mi*16)*FROW + (uint32_t)ks*32;
            LDSM4(a[mi][0], a[mi][1], a[mi][2], a[mi][3], addr);
        }
        uint32_t b[4][2];
#pragma unroll
        for (int nb=0;nb<2;nb++){
            uint32_t addr = sb + b_lane + (uint32_t)(nb*16)*FROW + (uint32_t)ks*32;
            LDSM4(b[2*nb][0], b[2*nb][1], b[2*nb+1][0], b[2*nb+1][1], addr);
        }
#pragma unroll
        for (int mi=0;mi<4;mi++)
#pragma unroll
            for (int nj=0;nj<4;nj++)
                MMA16816(acc[mi][nj], a[mi], b[nj]);
    }

    // epilogue: wh = fp16(W + acc*SCALING)
#pragma unroll
    for (int mi=0;mi<4;mi++){
        const int m = o0 + wmn*64 + mi*16 + (l >> 2);
#pragma unroll
        for (int nj=0;nj<4;nj++){
            const int n = i0 + wnn*32 + nj*8 + (l & 3)*2;
            float2 w01 = *reinterpret_cast<const float2*>(W + (size_t)m*D_IN + n);
            float2 w23 = *reinterpret_cast<const float2*>(W + (size_t)(m+8)*D_IN + n);
            __half2 h0 = __floats2half2_rn(w01.x + acc[mi][nj][0]*SCALING,
                                           w01.y + acc[mi][nj][1]*SCALING);
            __half2 h1 = __floats2half2_rn(w23.x + acc[mi][nj][2]*SCALING,
                                           w23.y + acc[mi][nj][3]*SCALING);
            *reinterpret_cast<__half2*>(g_wh + (size_t)m*D_IN + n)     = h0;
            *reinterpret_cast<__half2*>(g_wh + (size_t)(m+8)*D_IN + n) = h1;
        }
    }
}

// ---------- kernel 3: main GEMM via mma.sync (fp16, fp32 accum) ----------
// CTA tile 256(M) x 128(N), 16 warps (4x4), warp tile 64x32. K=4096, chunks of 64.
// 4-stage cp.async ring, ONE __syncthreads per chunk. 144B padded smem rows.
#define MT 256
#define NT 128
#define SROW 144
#define A_ST (MT*SROW)                 // 36864
#define B_ST (NT*SROW)                 // 18432
#define STG  (A_ST + B_ST)             // 55296
#define NSTAGE 4
#define GEMM_SMEM (NSTAGE*STG)         // 221184
#define NKI 64

__global__ void __launch_bounds__(512, 1)
lora_gemm_kernel(const float* __restrict__ bias, float* __restrict__ out){
    extern __shared__ char smem[];
    const uint32_t sbase = smem_u32(smem);
    const int tid = threadIdx.x;
    const int wid = tid >> 5;
    const int l   = tid & 31;
    const int wm  = wid & 3;    // 4 M-groups of 64
    const int wn  = wid >> 2;   // 4 N-groups of 32
    const int m0  = (int)(blockIdx.x >> 5) * MT;
    const int n0  = (int)(blockIdx.x & 31) * NT;

    float acc[4][4][4];
#pragma unroll
    for (int mi=0;mi<4;mi++)
#pragma unroll
        for (int nj=0;nj<4;nj++)
#pragma unroll
            for (int e=0;e<4;e++) acc[mi][nj][e] = 0.f;

    const int arow = tid >> 1, ah = tid & 1;       // A: 256 rows, 2 thr/row, 4x16B
    const int brow = tid >> 2, bq = tid & 3;       // B: 128 rows, 4 thr/row, 2x16B

    auto issue_load = [&](int kk){
        const int k0  = kk << 6;
        const uint32_t as = sbase + (uint32_t)(kk % NSTAGE) * STG;
        const uint32_t bs = as + A_ST;
        const __half* ga = g_xh + (size_t)(m0 + arow)*D_IN + k0 + ah*32;
        const uint32_t adst = as + (uint32_t)arow*SROW + (uint32_t)ah*64;
#pragma unroll
        for (int c=0;c<4;c++) cp16(adst + c*16, ga + c*8);
        const __half* gb = g_wh + (size_t)(n0 + brow)*D_IN + k0 + bq*16;
        const uint32_t bdst = bs + (uint32_t)brow*SROW + (uint32_t)bq*32;
#pragma unroll
        for (int c=0;c<2;c++) cp16(bdst + c*16, gb + c*8);
        asm volatile("cp.async.commit_group;" ::: "memory");
    };

    issue_load(0);
    issue_load(1);
    issue_load(2);

    const uint32_t a_lane = (uint32_t)(wm*64 + (l & 15)) * SROW + (uint32_t)((l >> 4) & 1) * 16;
    const uint32_t b_lane = (uint32_t)(wn*32 + (l & 7) + ((l >> 4) & 1)*8) * SROW
                          + (uint32_t)((l >> 3) & 1) * 16;

    for (int kk = 0; kk < NKI; kk++){
        asm volatile("cp.async.wait_group 2;" ::: "memory");
        __syncthreads();

        if (kk + 3 < NKI) issue_load(kk + 3);
        else asm volatile("cp.async.commit_group;" ::: "memory");

        const uint32_t as = sbase + (uint32_t)(kk % NSTAGE) * STG;
        const uint32_t bs = as + A_ST;

#pragma unroll
        for (int ks = 0; ks < 4; ks++){
            uint32_t a[4][4];
#pragma unroll
            for (int mi=0;mi<4;mi++){
                uint32_t addr = as + a_lane + (uint32_t)(mi*16)*SROW + (uint32_t)ks*32;
                LDSM4(a[mi][0], a[mi][1], a[mi][2], a[mi][3], addr);
            }
            uint32_t b[4][2];
#pragma unroll
            for (int nb=0;nb<2;nb++){
                uint32_t addr = bs + b_lane + (uint32_t)(nb*16)*SROW + (uint32_t)ks*32;
                LDSM4(b[2*nb][0], b[2*nb][1], b[2*nb+1][0], b[2*nb+1][1], addr);
            }
#pragma unroll
            for (int mi=0;mi<4;mi++)
#pragma unroll
                for (int nj=0;nj<4;nj++)
                    MMA16816(acc[mi][nj], a[mi], b[nj]);
        }
    }

    // epilogue: add bias, store fp32
#pragma unroll
    for (int mi=0;mi<4;mi++){
        const int m = m0 + wm*64 + mi*16 + (l >> 2);
#pragma unroll
        for (int nj=0;nj<4;nj++){
            const int n = n0 + wn*32 + nj*8 + (l & 3)*2;
            const float b0 = bias[n], b1 = bias[n+1];
            float2 v0 = make_float2(acc[mi][nj][0] + b0, acc[mi][nj][1] + b1);
            float2 v1 = make_float2(acc[mi][nj][2] + b0, acc[mi][nj][3] + b1);
            *reinterpret_cast<float2*>(out + (size_t)m*D_OUT + n)       = v0;
            *reinterpret_cast<float2*>(out + (size_t)(m+8)*D_OUT + n)   = v1;
        }
    }
}

// ---------- launch ----------
extern "C" void kernel_launch(void* const* d_in, const int* in_sizes, int n_in,
                              void* d_out, int out_size){
    const float* x  = (const float*)d_in[0];
    const float* W  = (const float*)d_in[1];
    const float* b  = (const float*)d_in[2];
    const float* lA = (const float*)d_in[3];
    const float* lB = (const float*)d_in[4];
    float* out = (float*)d_out;

    static bool attr_set = false;
    if (!attr_set){
        cudaFuncSetAttribute(lora_gemm_kernel,
                             cudaFuncAttributeMaxDynamicSharedMemorySize, GEMM_SMEM);
        cudaFuncSetAttribute(fold_x_kernel,
                             cudaFuncAttributeMaxDynamicSharedMemorySize, FOLD_SMEM);
        attr_set = true;
    }

    prep_kernel<<<(2*(size_t)D_IN*K_LORA + 255)/256, 256>>>(lA, lB);
    fold_x_kernel<<<1024 + NCONV, 256, FOLD_SMEM>>>(W, x);
    lora_gemm_kernel<<<(N_ROWS/MT)*(D_OUT/NT), 512, GEMM_SMEM>>>(b, out);
}